// round 4
// baseline (speedup 1.0000x reference)
#include <cuda_runtime.h>
#include <cstdint>

constexpr int B = 2, H = 16, S = 2048, D = 64;
constexpr int TQ = 16;     // q rows per CTA
constexpr int TK = 64;     // k rows per smem tile
constexpr int NT = 256;    // threads per CTA
constexpr int WPAD = 2052; // padded logit row stride (floats): breaks bank conflicts, 16B-aligned

#define FMA2(d, a, b, c) asm("fma.rn.f32x2 %0,%1,%2,%3;" : "=l"(d) : "l"(a), "l"(b), "l"(c))
#define PACK2(d, x, y)   asm("mov.b64 %0,{%1,%2};" : "=l"(d) : "f"(x), "f"(y))
#define UNPK2(x, y, d)   asm("mov.b64 {%0,%1},%2;" : "=f"(x), "=f"(y) : "l"(d))

__global__ __launch_bounds__(NT, 1)
void sdpa_tiled(const float* __restrict__ q,
                const float* __restrict__ k,
                const float* __restrict__ v,
                const uint32_t* __restrict__ mask,
                float* __restrict__ out,    // [B,H,S,D]
                float* __restrict__ wout)   // [B,H,S,S]
{
    extern __shared__ float sm[];
    float* wsm = sm;                      // [TQ][WPAD]  logits
    float* ksh = sm + TQ * WPAD;          // [2][TK*D]   K tiles (aliased by PV partials later)

    __shared__ float rowinv[TQ];
    __shared__ int   smode;

    const int tid  = threadIdx.x;
    const int lane = tid & 31;
    const int wid  = tid >> 5;

    const int bx = blockIdx.x;
    const int bh = bx >> 7;               // S/TQ = 128 q-tiles per (b,h)
    const int q0 = (bx & 127) * TQ;
    const int b  = bh >> 4;               // H = 16

    // ---- probe mask element width (bool may arrive as int32 or bytes) ----
    if (tid == 0) {
        int wide = 1;
        for (int i = 0; i < 256; i++) {
            uint32_t x = mask[i];
            if (x > 1u) { wide = (x == 0x3F800000u) ? 1 : 0; break; }
        }
        smode = wide;
    }

    // ---- load this lane's q row (scaled), packed as f32x2 ----
    const int row = lane & 15;
    const int jsel = lane >> 4;
    const float* qptr = q + ((size_t)bh * S + q0 + row) * D;
    unsigned long long q2[32];
    #pragma unroll
    for (int t = 0; t < 16; t++) {
        float4 f = reinterpret_cast<const float4*>(qptr)[t];
        f.x *= 0.125f; f.y *= 0.125f; f.z *= 0.125f; f.w *= 0.125f;
        PACK2(q2[2 * t],     f.x, f.y);
        PACK2(q2[2 * t + 1], f.z, f.w);
    }

    // ================= QK^T : logits -> smem =================
    const float* kbase = k + (size_t)bh * S * D;
    float4 pf[4];
    #pragma unroll
    for (int i = 0; i < 4; i++)
        pf[i] = reinterpret_cast<const float4*>(kbase)[i * 256 + tid];
    #pragma unroll
    for (int i = 0; i < 4; i++)
        reinterpret_cast<float4*>(ksh)[i * 256 + tid] = pf[i];
    __syncthreads();

    constexpr int NTILE = S / TK;  // 32
    for (int jt = 0; jt < NTILE; jt++) {
        const int buf = jt & 1;
        if (jt < NTILE - 1) {
            const float4* src = reinterpret_cast<const float4*>(kbase + (size_t)(jt + 1) * TK * D);
            #pragma unroll
            for (int i = 0; i < 4; i++) pf[i] = src[i * 256 + tid];
        }
        const float* kb = ksh + buf * (TK * D);
        #pragma unroll
        for (int it = 0; it < 4; it++) {
            const int jl = it * 16 + wid * 2 + jsel;
            const ulonglong2* kr = reinterpret_cast<const ulonglong2*>(kb + jl * D);
            unsigned long long a0 = 0ull, a1 = 0ull, a2 = 0ull, a3 = 0ull;
            #pragma unroll
            for (int t = 0; t < 16; t += 2) {
                ulonglong2 ka = kr[t];
                ulonglong2 kc = kr[t + 1];
                FMA2(a0, q2[2 * t],     ka.x, a0);
                FMA2(a1, q2[2 * t + 1], ka.y, a1);
                FMA2(a2, q2[2 * t + 2], kc.x, a2);
                FMA2(a3, q2[2 * t + 3], kc.y, a3);
            }
            float x0, x1, x2, x3, x4, x5, x6, x7;
            UNPK2(x0, x1, a0); UNPK2(x2, x3, a1);
            UNPK2(x4, x5, a2); UNPK2(x6, x7, a3);
            wsm[row * WPAD + jt * TK + jl] = ((x0 + x1) + (x2 + x3)) + ((x4 + x5) + (x6 + x7));
        }
        if (jt < NTILE - 1) {
            float* dst = ksh + (1 - buf) * (TK * D);
            #pragma unroll
            for (int i = 0; i < 4; i++)
                reinterpret_cast<float4*>(dst)[i * 256 + tid] = pf[i];
        }
        __syncthreads();
    }

    // ============ softmax sweeps: each warp owns rows 2w, 2w+1 ============
    const int wide = smode;
    #pragma unroll
    for (int rr = 0; rr < 2; rr++) {
        const int r = wid * 2 + rr;
        float* wr = wsm + r * WPAD;
        float4* wr4 = reinterpret_cast<float4*>(wr);

        // pass 1: mask + row max
        float mx = -3.4e38f;
        if (wide) {
            const int4* m4 = reinterpret_cast<const int4*>(mask + ((size_t)b * S + q0 + r) * S);
            for (int t = lane; t < S / 4; t += 32) {
                float4 x = wr4[t];
                int4 m = m4[t];
                if (m.x) x.x = -1e-9f;
                if (m.y) x.y = -1e-9f;
                if (m.z) x.z = -1e-9f;
                if (m.w) x.w = -1e-9f;
                mx = fmaxf(mx, fmaxf(fmaxf(x.x, x.y), fmaxf(x.z, x.w)));
                wr4[t] = x;
            }
        } else {
            const uchar4* m4 = reinterpret_cast<const uchar4*>(
                reinterpret_cast<const unsigned char*>(mask) + ((size_t)b * S + q0 + r) * S);
            for (int t = lane; t < S / 4; t += 32) {
                float4 x = wr4[t];
                uchar4 m = m4[t];
                if (m.x) x.x = -1e-9f;
                if (m.y) x.y = -1e-9f;
                if (m.z) x.z = -1e-9f;
                if (m.w) x.w = -1e-9f;
                mx = fmaxf(mx, fmaxf(fmaxf(x.x, x.y), fmaxf(x.z, x.w)));
                wr4[t] = x;
            }
        }
        #pragma unroll
        for (int o = 16; o; o >>= 1) mx = fmaxf(mx, __shfl_xor_sync(0xffffffffu, mx, o));

        // pass 2: exp + sum (store unnormalized exp)
        float sum = 0.f;
        for (int t = lane; t < S / 4; t += 32) {
            float4 x = wr4[t];
            x.x = __expf(x.x - mx); x.y = __expf(x.y - mx);
            x.z = __expf(x.z - mx); x.w = __expf(x.w - mx);
            sum += (x.x + x.y) + (x.z + x.w);
            wr4[t] = x;
        }
        #pragma unroll
        for (int o = 16; o; o >>= 1) sum += __shfl_xor_sync(0xffffffffu, sum, o);
        const float inv = 1.f / sum;
        if (lane == 0) rowinv[r] = inv;

        // pass 3: normalized weights -> gmem (coalesced float4)
        float4* go = reinterpret_cast<float4*>(wout + ((size_t)bh * S + q0 + r) * S);
        for (int t = lane; t < S / 4; t += 32) {
            float4 x = wr4[t];
            x.x *= inv; x.y *= inv; x.z *= inv; x.w *= inv;
            go[t] = x;
        }
    }
    __syncthreads();

    // ================= PV : out = softmax(W) @ V =================
    // thread -> (d4: float4 of d, rq: 4-row block, jq: j quarter)
    {
        const int d4 = tid & 15;
        const int rq = (tid >> 4) & 3;
        const int jq = tid >> 6;
        const ulonglong2* vb = reinterpret_cast<const ulonglong2*>(v + (size_t)bh * S * D);

        unsigned long long acc[8];
        #pragma unroll
        for (int i = 0; i < 8; i++) acc[i] = 0ull;

        const float* w0 = wsm + (rq * 4 + 0) * WPAD;
        const float* w1 = wsm + (rq * 4 + 1) * WPAD;
        const float* w2 = wsm + (rq * 4 + 2) * WPAD;
        const float* w3 = wsm + (rq * 4 + 3) * WPAD;

        const int jend = jq * 512 + 512;
        for (int j = jq * 512; j < jend; j += 4) {
            float wa[4], wb[4], wc[4], wd[4];
            *reinterpret_cast<float4*>(wa) = *reinterpret_cast<const float4*>(w0 + j);
            *reinterpret_cast<float4*>(wb) = *reinterpret_cast<const float4*>(w1 + j);
            *reinterpret_cast<float4*>(wc) = *reinterpret_cast<const float4*>(w2 + j);
            *reinterpret_cast<float4*>(wd) = *reinterpret_cast<const float4*>(w3 + j);
            #pragma unroll
            for (int jj = 0; jj < 4; jj++) {
                ulonglong2 v2 = vb[(size_t)(j + jj) * 16 + d4];
                unsigned long long p;
                PACK2(p, wa[jj], wa[jj]); FMA2(acc[0], p, v2.x, acc[0]); FMA2(acc[1], p, v2.y, acc[1]);
                PACK2(p, wb[jj], wb[jj]); FMA2(acc[2], p, v2.x, acc[2]); FMA2(acc[3], p, v2.y, acc[3]);
                PACK2(p, wc[jj], wc[jj]); FMA2(acc[4], p, v2.x, acc[4]); FMA2(acc[5], p, v2.y, acc[5]);
                PACK2(p, wd[jj], wd[jj]); FMA2(acc[6], p, v2.x, acc[6]); FMA2(acc[7], p, v2.y, acc[7]);
            }
        }

        __syncthreads();   // ksh region is dead; reuse as PV partial buffer
        float4* pred = reinterpret_cast<float4*>(ksh);  // [4(jq)][16(row)][16(d4)] float4
        #pragma unroll
        for (int rr = 0; rr < 4; rr++) {
            float4 o;
            UNPK2(o.x, o.y, acc[2 * rr]);
            UNPK2(o.z, o.w, acc[2 * rr + 1]);
            pred[(jq * 16 + rq * 4 + rr) * 16 + d4] = o;
        }
    }
    __syncthreads();

    // cross-jq reduce + scale + write out
    {
        const int r  = tid >> 4;
        const int dd = tid & 15;
        const float4* pred = reinterpret_cast<const float4*>(ksh);
        float4 o = pred[(0 * 16 + r) * 16 + dd];
        #pragma unroll
        for (int jq = 1; jq < 4; jq++) {
            float4 p = pred[(jq * 16 + r) * 16 + dd];
            o.x += p.x; o.y += p.y; o.z += p.z; o.w += p.w;
        }
        const float inv = rowinv[r];
        o.x *= inv; o.y *= inv; o.z *= inv; o.w *= inv;
        reinterpret_cast<float4*>(out + ((size_t)bh * S + q0 + r) * D)[dd] = o;
    }
}

extern "C" void kernel_launch(void* const* d_in, const int* in_sizes, int n_in,
                              void* d_out, int out_size)
{
    const float* q = (const float*)d_in[0];
    const float* k = (const float*)d_in[1];
    const float* v = (const float*)d_in[2];
    const uint32_t* mask = (const uint32_t*)d_in[3];

    float* out  = (float*)d_out;
    float* wout = out + (size_t)B * H * S * D;

    constexpr int SMEM = (TQ * WPAD + 2 * TK * D) * 4;  // 164,096 B
    static bool configured = false;
    if (!configured) {
        cudaFuncSetAttribute(sdpa_tiled, cudaFuncAttributeMaxDynamicSharedMemorySize, SMEM);
        configured = true;
    }
    sdpa_tiled<<<B * H * (S / TQ), NT, SMEM>>>(q, k, v, mask, out, wout);
}

// round 6
// speedup vs baseline: 1.7330x; 1.7330x over previous
#include <cuda_runtime.h>
#include <cstdint>

constexpr int B = 2, H = 16, S = 2048, D = 64;
constexpr int NT = 256;                       // 8 warps
constexpr float SCALE = 0.125f * 1.4426950408889634f;  // (1/sqrt(64))*log2(e)

__device__ unsigned char g_m8[(size_t)B * S * S];      // byte mask (0/1)

// ---- smem map (bytes) ----
constexpr int PADK = 68;   // K/V/Q row pad (floats)
constexpr int PADW = 132;  // W row pad (floats)
constexpr int SM_Q = 0;                       // [128][68] f32
constexpr int SM_K = 34816;                   // [128][68]
constexpr int SM_V = 69632;                   // [128][68]
constexpr int SM_W = 104448;                  // [128][132]
constexpr int SM_S = 172032;                  // 512 floats: [0..255] partials, [256..383] inv
constexpr int SMEM_TOT = 174080;

__device__ __forceinline__ float tf32_rna(float x) {
    uint32_t b; asm("cvt.rna.tf32.f32 %0, %1;" : "=r"(b) : "f"(x));
    return __uint_as_float(b);
}
__device__ __forceinline__ float ex2f(float x) {
    float y; asm("ex2.approx.ftz.f32 %0, %1;" : "=f"(y) : "f"(x)); return y;
}
__device__ __forceinline__ void mma8(float* c, uint32_t a0, uint32_t a1, uint32_t a2, uint32_t a3,
                                     uint32_t b0, uint32_t b1) {
    asm volatile("mma.sync.aligned.m16n8k8.row.col.f32.tf32.tf32.f32 "
                 "{%0,%1,%2,%3},{%4,%5,%6,%7},{%8,%9},{%0,%1,%2,%3};"
                 : "+f"(c[0]), "+f"(c[1]), "+f"(c[2]), "+f"(c[3])
                 : "r"(a0), "r"(a1), "r"(a2), "r"(a3), "r"(b0), "r"(b1));
}
__device__ __forceinline__ uint32_t f2u(float x) { return __float_as_uint(x); }

// ---------------- pre-kernel: mask -> bytes (handles int32 or byte bool) ----------------
__global__ __launch_bounds__(256) void mask8k(const uint32_t* __restrict__ m) {
    __shared__ int swide;
    const int t = threadIdx.x;
    const size_t row = blockIdx.x;
    if (t == 0) {
        int wide = 1;
        for (int i = 0; i < 256; i++) {
            uint32_t x = m[i];
            if (x > 1u) { wide = (x == 0x3F800000u) ? 1 : 0; break; }
        }
        swide = wide;
    }
    __syncthreads();
    uint32_t* dst = reinterpret_cast<uint32_t*>(g_m8 + row * S);
    if (swide) {
        const uint4* src = reinterpret_cast<const uint4*>(m + row * S);
        #pragma unroll
        for (int i = 0; i < 2; i++) {
            int idx = i * 256 + t;
            uint4 x = src[idx];
            dst[idx] = (x.x ? 1u : 0u) | ((x.y ? 1u : 0u) << 8) |
                       ((x.z ? 1u : 0u) << 16) | ((x.w ? 1u : 0u) << 24);
        }
    } else {
        const uint32_t* src = reinterpret_cast<const uint32_t*>(
            reinterpret_cast<const unsigned char*>(m) + row * S);
        #pragma unroll
        for (int i = 0; i < 2; i++) {
            int idx = i * 256 + t;
            uint32_t x = src[idx];
            dst[idx] = ((x & 0xFFu) ? 1u : 0u) | (((x >> 8) & 0xFFu) ? 0x100u : 0u) |
                       (((x >> 16) & 0xFFu) ? 0x10000u : 0u) | ((x >> 24) ? 0x1000000u : 0u);
        }
    }
}

// ---------------- main kernel ----------------
__global__ __launch_bounds__(NT, 1)
void sdpa_mma(const float* __restrict__ q, const float* __restrict__ k,
              const float* __restrict__ v,
              float* __restrict__ out, float* __restrict__ wout)
{
    extern __shared__ char sm[];
    float* Qs = reinterpret_cast<float*>(sm + SM_Q);
    float* Ks = reinterpret_cast<float*>(sm + SM_K);
    float* Vs = reinterpret_cast<float*>(sm + SM_V);
    float* Ws = reinterpret_cast<float*>(sm + SM_W);
    float* Sr = reinterpret_cast<float*>(sm + SM_S);   // partial sums + inv

    const int tid = threadIdx.x, lane = tid & 31, wid = tid >> 5;
    const int wm = wid & 3, wn = wid >> 2;             // warp grid 4(m) x 2(n)
    const int ty = lane >> 2, tx = lane & 3;

    const int bx = blockIdx.x, bh = bx >> 4, q0 = (bx & 15) * 128, b = bh >> 4;

    // ---- stage Q once (scaled, rna) ----
    {
        const float4* qg = reinterpret_cast<const float4*>(q + ((size_t)bh * S + q0) * D);
        #pragma unroll
        for (int i = 0; i < 8; i++) {
            int idx = i * 256 + tid;
            int r = idx >> 4, c4 = (idx & 15) * 4;
            float4 x = qg[idx];
            x.x = tf32_rna(x.x * SCALE); x.y = tf32_rna(x.y * SCALE);
            x.z = tf32_rna(x.z * SCALE); x.w = tf32_rna(x.w * SCALE);
            *reinterpret_cast<float4*>(Qs + r * PADK + c4) = x;
        }
    }

    float pacc[2][4][4];                               // PV accum [mt][nt][4]
    #pragma unroll
    for (int a = 0; a < 2; a++)
        #pragma unroll
        for (int n = 0; n < 4; n++)
            #pragma unroll
            for (int i = 0; i < 4; i++) pacc[a][n][i] = 0.f;
    float er4[4] = {0.f, 0.f, 0.f, 0.f};               // row-sum partials

    const unsigned char* mbase = g_m8 + ((size_t)b * S + q0) * S;

    for (int jt = 0; jt < 16; jt++) {
        const int j0 = jt * 128;

        // ---- stage K, V tiles (rna) ----
        {
            const float4* kg = reinterpret_cast<const float4*>(k + ((size_t)bh * S + j0) * D);
            const float4* vg = reinterpret_cast<const float4*>(v + ((size_t)bh * S + j0) * D);
            #pragma unroll
            for (int i = 0; i < 8; i++) {
                int idx = i * 256 + tid;
                int r = idx >> 4, c4 = (idx & 15) * 4;
                float4 x = kg[idx];
                x.x = tf32_rna(x.x); x.y = tf32_rna(x.y);
                x.z = tf32_rna(x.z); x.w = tf32_rna(x.w);
                *reinterpret_cast<float4*>(Ks + r * PADK + c4) = x;
                float4 y = vg[idx];
                y.x = tf32_rna(y.x); y.y = tf32_rna(y.y);
                y.z = tf32_rna(y.z); y.w = tf32_rna(y.w);
                *reinterpret_cast<float4*>(Vs + r * PADK + c4) = y;
            }
        }
        __syncthreads();

        // ---- QK^T: C[128x128] = Q @ K^T ----
        float cacc[2][8][4];
        #pragma unroll
        for (int a = 0; a < 2; a++)
            #pragma unroll
            for (int n = 0; n < 8; n++)
                #pragma unroll
                for (int i = 0; i < 4; i++) cacc[a][n][i] = 0.f;

        #pragma unroll
        for (int ks = 0; ks < 8; ks++) {
            uint32_t a0[2], a1[2], a2[2], a3[2];
            #pragma unroll
            for (int mt = 0; mt < 2; mt++) {
                const float* qa = Qs + (wm * 32 + mt * 16 + ty) * PADK + ks * 8 + tx;
                a0[mt] = f2u(qa[0]);
                a1[mt] = f2u(qa[8 * PADK]);
                a2[mt] = f2u(qa[4]);
                a3[mt] = f2u(qa[8 * PADK + 4]);
            }
            #pragma unroll
            for (int nt = 0; nt < 8; nt++) {
                const float* kb = Ks + (wn * 64 + nt * 8 + ty) * PADK + ks * 8 + tx;
                uint32_t b0 = f2u(kb[0]), b1 = f2u(kb[4]);
                mma8(cacc[0][nt], a0[0], a1[0], a2[0], a3[0], b0, b1);
                mma8(cacc[1][nt], a0[1], a1[1], a2[1], a3[1], b0, b1);
            }
        }

        // ---- mask + exp -> Ws (rna), accumulate row sums ----
        #pragma unroll
        for (int mt = 0; mt < 2; mt++) {
            const int r0 = wm * 32 + mt * 16 + ty;
            const int r1 = r0 + 8;
            const unsigned char* m0 = mbase + (size_t)r0 * S + j0 + wn * 64;
            const unsigned char* m1 = mbase + (size_t)r1 * S + j0 + wn * 64;
            #pragma unroll
            for (int nt = 0; nt < 8; nt++) {
                const int cl = wn * 64 + nt * 8 + tx * 2;
                unsigned short w0 = *reinterpret_cast<const unsigned short*>(m0 + nt * 8 + tx * 2);
                unsigned short w1 = *reinterpret_cast<const unsigned short*>(m1 + nt * 8 + tx * 2);
                float e00 = (w0 & 0xFFu) ? 1.0f : ex2f(cacc[mt][nt][0]);
                float e01 = (w0 >> 8)    ? 1.0f : ex2f(cacc[mt][nt][1]);
                float e10 = (w1 & 0xFFu) ? 1.0f : ex2f(cacc[mt][nt][2]);
                float e11 = (w1 >> 8)    ? 1.0f : ex2f(cacc[mt][nt][3]);
                e00 = tf32_rna(e00); e01 = tf32_rna(e01);
                e10 = tf32_rna(e10); e11 = tf32_rna(e11);
                er4[mt * 2 + 0] += e00 + e01;
                er4[mt * 2 + 1] += e10 + e11;
                *reinterpret_cast<float2*>(Ws + r0 * PADW + cl) = make_float2(e00, e01);
                *reinterpret_cast<float2*>(Ws + r1 * PADW + cl) = make_float2(e10, e11);
            }
        }
        __syncthreads();

        // ---- unnormalized W tile -> gmem (coalesced, streaming) ----
        {
            float* wg = wout + ((size_t)bh * S + q0) * S + j0;
            #pragma unroll
            for (int i = 0; i < 16; i++) {
                int idx = i * 256 + tid;
                int r = idx >> 5, c4 = (idx & 31) * 4;
                float4 x = *reinterpret_cast<const float4*>(Ws + r * PADW + c4);
                __stcs(reinterpret_cast<float4*>(wg + (size_t)r * S + c4), x);
            }
        }

        // ---- PV: acc += W_tile @ V_tile ----
        #pragma unroll
        for (int kk = 0; kk < 16; kk++) {
            uint32_t a0[2], a1[2], a2[2], a3[2];
            #pragma unroll
            for (int mt = 0; mt < 2; mt++) {
                const float* wa = Ws + (wm * 32 + mt * 16 + ty) * PADW + kk * 8 + tx;
                a0[mt] = f2u(wa[0]);
                a1[mt] = f2u(wa[8 * PADW]);
                a2[mt] = f2u(wa[4]);
                a3[mt] = f2u(wa[8 * PADW + 4]);
            }
            #pragma unroll
            for (int nt = 0; nt < 4; nt++) {
                const float* vb = Vs + (kk * 8 + tx) * PADK + wn * 32 + nt * 8 + ty;
                uint32_t b0 = f2u(vb[0]), b1 = f2u(vb[4 * PADK]);
                mma8(pacc[0][nt], a0[0], a1[0], a2[0], a3[0], b0, b1);
                mma8(pacc[1][nt], a0[1], a1[1], a2[1], a3[1], b0, b1);
            }
        }
        __syncthreads();
    }

    // ---- row-sum reduction -> inv ----
    #pragma unroll
    for (int i = 0; i < 4; i++) {
        er4[i] += __shfl_xor_sync(0xffffffffu, er4[i], 1);
        er4[i] += __shfl_xor_sync(0xffffffffu, er4[i], 2);
    }
    if (tx == 0) {
        #pragma unroll
        for (int i = 0; i < 4; i++) {
            int r = wm * 32 + (i >> 1) * 16 + ty + (i & 1) * 8;
            Sr[wn * 128 + r] = er4[i];
        }
    }
    __syncthreads();
    if (tid < 128) Sr[256 + tid] = 1.0f / (Sr[tid] + Sr[128 + tid]);
    __syncthreads();
    const float* sinv = Sr + 256;

    // ---- write PV out (scaled) ----
    #pragma unroll
    for (int mt = 0; mt < 2; mt++) {
        const int r0 = wm * 32 + mt * 16 + ty;
        const int r1 = r0 + 8;
        const float i0 = sinv[r0], i1 = sinv[r1];
        float* o0 = out + ((size_t)bh * S + q0 + r0) * D;
        float* o1 = out + ((size_t)bh * S + q0 + r1) * D;
        #pragma unroll
        for (int nt = 0; nt < 4; nt++) {
            const int c = wn * 32 + nt * 8 + tx * 2;
            *reinterpret_cast<float2*>(o0 + c) =
                make_float2(pacc[mt][nt][0] * i0, pacc[mt][nt][1] * i0);
            *reinterpret_cast<float2*>(o1 + c) =
                make_float2(pacc[mt][nt][2] * i1, pacc[mt][nt][3] * i1);
        }
    }

    // ---- normalize this CTA's W block in place ----
    {
        float* wg = wout + ((size_t)bh * S + q0) * S;
        #pragma unroll 4
        for (int i = 0; i < 256; i++) {
            int idx = i * 256 + tid;
            int r = idx >> 9, c4 = (idx & 511) * 4;
            float4* p = reinterpret_cast<float4*>(wg + (size_t)r * S + c4);
            float4 x = __ldcs(p);
            const float iv = sinv[r];
            x.x *= iv; x.y *= iv; x.z *= iv; x.w *= iv;
            __stcs(p, x);
        }
    }
}

extern "C" void kernel_launch(void* const* d_in, const int* in_sizes, int n_in,
                              void* d_out, int out_size)
{
    const float* q = (const float*)d_in[0];
    const float* k = (const float*)d_in[1];
    const float* v = (const float*)d_in[2];
    const uint32_t* mask = (const uint32_t*)d_in[3];

    float* out  = (float*)d_out;
    float* wout = out + (size_t)B * H * S * D;

    static bool configured = false;
    if (!configured) {
        cudaFuncSetAttribute(sdpa_mma, cudaFuncAttributeMaxDynamicSharedMemorySize, SMEM_TOT);
        configured = true;
    }
    mask8k<<<B * S, 256>>>(mask);
    sdpa_mma<<<B * H * 16, NT, SMEM_TOT>>>(q, k, v, out, wout);
}

// round 7
// speedup vs baseline: 2.6796x; 1.5462x over previous
#include <cuda_runtime.h>
#include <cstdint>

constexpr int B = 2, H = 16, S = 2048, D = 64;
constexpr int NT = 512;                       // 16 warps
constexpr float SCALE = 0.125f * 1.4426950408889634f;  // (1/sqrt(64))*log2(e)

__device__ unsigned char g_m8[(size_t)B * S * S];      // byte mask (0/1)

// ---- smem map (bytes) ----
constexpr int PADK = 68;   // K/V/Q row pad (floats)
constexpr int PADW = 132;  // W row pad (floats)
constexpr int SM_Q = 0;                       // [128][68] f32
constexpr int SM_K = 34816;                   // [128][68]
constexpr int SM_V = 69632;                   // [128][68]
constexpr int SM_W = 104448;                  // [128][132]
constexpr int SM_S = 172032;                  // 640 floats: [0..511] partials, [512..639] inv
constexpr int SMEM_TOT = 174592;

__device__ __forceinline__ float tf32_rna(float x) {
    uint32_t b; asm("cvt.rna.tf32.f32 %0, %1;" : "=r"(b) : "f"(x));
    return __uint_as_float(b);
}
__device__ __forceinline__ float ex2f(float x) {
    float y; asm("ex2.approx.ftz.f32 %0, %1;" : "=f"(y) : "f"(x)); return y;
}
__device__ __forceinline__ void mma8(float* c, uint32_t a0, uint32_t a1, uint32_t a2, uint32_t a3,
                                     uint32_t b0, uint32_t b1) {
    asm volatile("mma.sync.aligned.m16n8k8.row.col.f32.tf32.tf32.f32 "
                 "{%0,%1,%2,%3},{%4,%5,%6,%7},{%8,%9},{%0,%1,%2,%3};"
                 : "+f"(c[0]), "+f"(c[1]), "+f"(c[2]), "+f"(c[3])
                 : "r"(a0), "r"(a1), "r"(a2), "r"(a3), "r"(b0), "r"(b1));
}
__device__ __forceinline__ uint32_t f2u(float x) { return __float_as_uint(x); }
__device__ __forceinline__ float4 rna4(float4 x) {
    x.x = tf32_rna(x.x); x.y = tf32_rna(x.y);
    x.z = tf32_rna(x.z); x.w = tf32_rna(x.w);
    return x;
}

// ---------------- pre-kernel: mask -> bytes (handles int32 or byte bool) ----------------
__global__ __launch_bounds__(256) void mask8k(const uint32_t* __restrict__ m) {
    __shared__ int swide;
    const int t = threadIdx.x;
    const size_t row = blockIdx.x;
    if (t == 0) {
        int wide = 1;
        for (int i = 0; i < 256; i++) {
            uint32_t x = m[i];
            if (x > 1u) { wide = (x == 0x3F800000u) ? 1 : 0; break; }
        }
        swide = wide;
    }
    __syncthreads();
    uint32_t* dst = reinterpret_cast<uint32_t*>(g_m8 + row * S);
    if (swide) {
        const uint4* src = reinterpret_cast<const uint4*>(m + row * S);
        #pragma unroll
        for (int i = 0; i < 2; i++) {
            int idx = i * 256 + t;
            uint4 x = src[idx];
            dst[idx] = (x.x ? 1u : 0u) | ((x.y ? 1u : 0u) << 8) |
                       ((x.z ? 1u : 0u) << 16) | ((x.w ? 1u : 0u) << 24);
        }
    } else {
        const uint32_t* src = reinterpret_cast<const uint32_t*>(
            reinterpret_cast<const unsigned char*>(m) + row * S);
        #pragma unroll
        for (int i = 0; i < 2; i++) {
            int idx = i * 256 + t;
            uint32_t x = src[idx];
            dst[idx] = ((x & 0xFFu) ? 1u : 0u) | (((x >> 8) & 0xFFu) ? 0x100u : 0u) |
                       (((x >> 16) & 0xFFu) ? 0x10000u : 0u) | ((x >> 24) ? 0x1000000u : 0u);
        }
    }
}

// ---------------- main kernel ----------------
__global__ __launch_bounds__(NT, 1)
void sdpa_mma(const float* __restrict__ q, const float* __restrict__ k,
              const float* __restrict__ v,
              float* __restrict__ out, float* __restrict__ wout)
{
    extern __shared__ char sm[];
    float* Qs = reinterpret_cast<float*>(sm + SM_Q);
    float* Ks = reinterpret_cast<float*>(sm + SM_K);
    float* Vs = reinterpret_cast<float*>(sm + SM_V);
    float* Ws = reinterpret_cast<float*>(sm + SM_W);
    float* Sr = reinterpret_cast<float*>(sm + SM_S);

    const int tid = threadIdx.x, lane = tid & 31, wid = tid >> 5;
    const int wm = wid & 3, wn = wid >> 2;             // 4(m) x 4(n)
    const int ty = lane >> 2, tx = lane & 3;

    const int bx = blockIdx.x, bh = bx >> 4, q0 = (bx & 15) * 128, b = bh >> 4;

    // staging indices: 2048 float4 per 128x64 tile -> 4 per thread
    const int sr_ = tid >> 2;            // wrong granularity fix below
    (void)sr_;

    // ---- stage Q once (scaled, rna) ----
    {
        const float4* qg = reinterpret_cast<const float4*>(q + ((size_t)bh * S + q0) * D);
        #pragma unroll
        for (int i = 0; i < 4; i++) {
            int idx = i * NT + tid;
            int r = idx >> 4, c4 = (idx & 15) * 4;
            float4 x = qg[idx];
            x.x = tf32_rna(x.x * SCALE); x.y = tf32_rna(x.y * SCALE);
            x.z = tf32_rna(x.z * SCALE); x.w = tf32_rna(x.w * SCALE);
            *reinterpret_cast<float4*>(Qs + r * PADK + c4) = x;
        }
    }

    // ---- stage K/V tile 0 ----
    const float4* kg0 = reinterpret_cast<const float4*>(k + (size_t)bh * S * D);
    const float4* vg0 = reinterpret_cast<const float4*>(v + (size_t)bh * S * D);
    {
        #pragma unroll
        for (int i = 0; i < 4; i++) {
            int idx = i * NT + tid;
            int r = idx >> 4, c4 = (idx & 15) * 4;
            *reinterpret_cast<float4*>(Ks + r * PADK + c4) = rna4(kg0[idx]);
            *reinterpret_cast<float4*>(Vs + r * PADK + c4) = rna4(vg0[idx]);
        }
    }
    __syncthreads();

    float pacc[2][2][4];
    #pragma unroll
    for (int a = 0; a < 2; a++)
        #pragma unroll
        for (int n = 0; n < 2; n++)
            #pragma unroll
            for (int i = 0; i < 4; i++) pacc[a][n][i] = 0.f;
    float er4[4] = {0.f, 0.f, 0.f, 0.f};

    const unsigned char* mbase = g_m8 + ((size_t)b * S + q0) * S;

    float4 kpre[4], vpre[4];

    for (int jt = 0; jt < 16; jt++) {
        const int j0 = jt * 128;

        // ---- prefetch next tile into registers (latency hidden by compute) ----
        if (jt < 16 - 1) {
            const float4* kg = kg0 + (size_t)(j0 + 128) * (D / 4);
            const float4* vg = vg0 + (size_t)(j0 + 128) * (D / 4);
            #pragma unroll
            for (int i = 0; i < 4; i++) {
                kpre[i] = kg[i * NT + tid];
                vpre[i] = vg[i * NT + tid];
            }
        }

        // ---- QK^T: 32x32 block per warp ----
        float cacc[2][4][4];
        #pragma unroll
        for (int a = 0; a < 2; a++)
            #pragma unroll
            for (int n = 0; n < 4; n++)
                #pragma unroll
                for (int i = 0; i < 4; i++) cacc[a][n][i] = 0.f;

        #pragma unroll
        for (int ks = 0; ks < 8; ks++) {
            uint32_t a0[2], a1[2], a2[2], a3[2];
            #pragma unroll
            for (int mt = 0; mt < 2; mt++) {
                const float* qa = Qs + (wm * 32 + mt * 16 + ty) * PADK + ks * 8 + tx;
                a0[mt] = f2u(qa[0]);
                a1[mt] = f2u(qa[8 * PADK]);
                a2[mt] = f2u(qa[4]);
                a3[mt] = f2u(qa[8 * PADK + 4]);
            }
            #pragma unroll
            for (int nt = 0; nt < 4; nt++) {
                const float* kb = Ks + (wn * 32 + nt * 8 + ty) * PADK + ks * 8 + tx;
                uint32_t b0 = f2u(kb[0]), b1 = f2u(kb[4]);
                mma8(cacc[0][nt], a0[0], a1[0], a2[0], a3[0], b0, b1);
                mma8(cacc[1][nt], a0[1], a1[1], a2[1], a3[1], b0, b1);
            }
        }

        // ---- mask + exp -> Ws (rna), accumulate row sums ----
        #pragma unroll
        for (int mt = 0; mt < 2; mt++) {
            const int r0 = wm * 32 + mt * 16 + ty;
            const int r1 = r0 + 8;
            const unsigned char* m0 = mbase + (size_t)r0 * S + j0 + wn * 32;
            const unsigned char* m1 = mbase + (size_t)r1 * S + j0 + wn * 32;
            #pragma unroll
            for (int nt = 0; nt < 4; nt++) {
                const int cl = wn * 32 + nt * 8 + tx * 2;
                unsigned short w0 = *reinterpret_cast<const unsigned short*>(m0 + nt * 8 + tx * 2);
                unsigned short w1 = *reinterpret_cast<const unsigned short*>(m1 + nt * 8 + tx * 2);
                float e00 = (w0 & 0xFFu) ? 1.0f : ex2f(cacc[mt][nt][0]);
                float e01 = (w0 >> 8)    ? 1.0f : ex2f(cacc[mt][nt][1]);
                float e10 = (w1 & 0xFFu) ? 1.0f : ex2f(cacc[mt][nt][2]);
                float e11 = (w1 >> 8)    ? 1.0f : ex2f(cacc[mt][nt][3]);
                e00 = tf32_rna(e00); e01 = tf32_rna(e01);
                e10 = tf32_rna(e10); e11 = tf32_rna(e11);
                er4[mt * 2 + 0] += e00 + e01;
                er4[mt * 2 + 1] += e10 + e11;
                *reinterpret_cast<float2*>(Ws + r0 * PADW + cl) = make_float2(e00, e01);
                *reinterpret_cast<float2*>(Ws + r1 * PADW + cl) = make_float2(e10, e11);
            }
        }
        __syncthreads();

        // ---- unnormalized W tile -> gmem (coalesced, streaming) ----
        {
            float* wg = wout + ((size_t)bh * S + q0) * S + j0;
            #pragma unroll
            for (int i = 0; i < 8; i++) {
                int idx = i * NT + tid;
                int r = idx >> 5, c4 = (idx & 31) * 4;
                float4 x = *reinterpret_cast<const float4*>(Ws + r * PADW + c4);
                __stcs(reinterpret_cast<float4*>(wg + (size_t)r * S + c4), x);
            }
        }

        // ---- PV: acc += W_tile @ V_tile (16 cols per warp) ----
        #pragma unroll
        for (int kk = 0; kk < 16; kk++) {
            uint32_t a0[2], a1[2], a2[2], a3[2];
            #pragma unroll
            for (int mt = 0; mt < 2; mt++) {
                const float* wa = Ws + (wm * 32 + mt * 16 + ty) * PADW + kk * 8 + tx;
                a0[mt] = f2u(wa[0]);
                a1[mt] = f2u(wa[8 * PADW]);
                a2[mt] = f2u(wa[4]);
                a3[mt] = f2u(wa[8 * PADW + 4]);
            }
            #pragma unroll
            for (int nt = 0; nt < 2; nt++) {
                const float* vb = Vs + (kk * 8 + tx) * PADK + wn * 16 + nt * 8 + ty;
                uint32_t b0 = f2u(vb[0]), b1 = f2u(vb[4 * PADK]);
                mma8(pacc[0][nt], a0[0], a1[0], a2[0], a3[0], b0, b1);
                mma8(pacc[1][nt], a0[1], a1[1], a2[1], a3[1], b0, b1);
            }
        }
        __syncthreads();

        // ---- store prefetched tile to smem ----
        if (jt < 16 - 1) {
            #pragma unroll
            for (int i = 0; i < 4; i++) {
                int idx = i * NT + tid;
                int r = idx >> 4, c4 = (idx & 15) * 4;
                *reinterpret_cast<float4*>(Ks + r * PADK + c4) = rna4(kpre[i]);
                *reinterpret_cast<float4*>(Vs + r * PADK + c4) = rna4(vpre[i]);
            }
            __syncthreads();
        }
    }

    // ---- row-sum reduction -> inv ----
    #pragma unroll
    for (int i = 0; i < 4; i++) {
        er4[i] += __shfl_xor_sync(0xffffffffu, er4[i], 1);
        er4[i] += __shfl_xor_sync(0xffffffffu, er4[i], 2);
    }
    if (tx == 0) {
        #pragma unroll
        for (int i = 0; i < 4; i++) {
            int r = wm * 32 + (i >> 1) * 16 + ty + (i & 1) * 8;
            Sr[wn * 128 + r] = er4[i];
        }
    }
    __syncthreads();
    if (tid < 128)
        Sr[512 + tid] = 1.0f / (Sr[tid] + Sr[128 + tid] + Sr[256 + tid] + Sr[384 + tid]);
    __syncthreads();
    const float* sinv = Sr + 512;

    // ---- write PV out (scaled) ----
    #pragma unroll
    for (int mt = 0; mt < 2; mt++) {
        const int r0 = wm * 32 + mt * 16 + ty;
        const int r1 = r0 + 8;
        const float i0 = sinv[r0], i1 = sinv[r1];
        float* o0 = out + ((size_t)bh * S + q0 + r0) * D;
        float* o1 = out + ((size_t)bh * S + q0 + r1) * D;
        #pragma unroll
        for (int nt = 0; nt < 2; nt++) {
            const int c = wn * 16 + nt * 8 + tx * 2;
            *reinterpret_cast<float2*>(o0 + c) =
                make_float2(pacc[mt][nt][0] * i0, pacc[mt][nt][1] * i0);
            *reinterpret_cast<float2*>(o1 + c) =
                make_float2(pacc[mt][nt][2] * i1, pacc[mt][nt][3] * i1);
        }
    }

    // ---- normalize this CTA's W block in place (streaming) ----
    {
        float* wg = wout + ((size_t)bh * S + q0) * S;
        #pragma unroll 4
        for (int i = 0; i < 128; i++) {
            int idx = i * NT + tid;
            int r = idx >> 9, c4 = (idx & 511) * 4;
            float4* p = reinterpret_cast<float4*>(wg + (size_t)r * S + c4);
            float4 x = __ldcs(p);
            const float iv = sinv[r];
            x.x *= iv; x.y *= iv; x.z *= iv; x.w *= iv;
            __stcs(p, x);
        }
    }
}

extern "C" void kernel_launch(void* const* d_in, const int* in_sizes, int n_in,
                              void* d_out, int out_size)
{
    const float* q = (const float*)d_in[0];
    const float* k = (const float*)d_in[1];
    const float* v = (const float*)d_in[2];
    const uint32_t* mask = (const uint32_t*)d_in[3];

    float* out  = (float*)d_out;
    float* wout = out + (size_t)B * H * S * D;

    static bool configured = false;
    if (!configured) {
        cudaFuncSetAttribute(sdpa_mma, cudaFuncAttributeMaxDynamicSharedMemorySize, SMEM_TOT);
        configured = true;
    }
    mask8k<<<B * S, 256>>>(mask);
    sdpa_mma<<<B * H * 16, NT, SMEM_TOT>>>(q, k, v, out, wout);
}

// round 8
// speedup vs baseline: 2.7282x; 1.0181x over previous
#include <cuda_runtime.h>
#include <cstdint>

constexpr int B = 2, H = 16, S = 2048, D = 64;
constexpr int NT = 512;                       // 16 warps
constexpr float SCALE = 0.125f * 1.4426950408889634f;  // (1/sqrt(64))*log2(e)

__device__ unsigned char g_m8[(size_t)B * S * S];      // byte mask (0/1)

// ---- smem map (bytes) ----
constexpr int PADK = 68;   // K/V/Q row pad (floats)
constexpr int PADW = 132;  // W row pad (floats)
constexpr int SM_Q = 0;                       // [128][68] f32
constexpr int SM_K = 34816;                   // [128][68]
constexpr int SM_V = 69632;                   // [128][68]
constexpr int SM_W = 104448;                  // [128][132]
constexpr int SM_S = 172032;                  // 640 floats
constexpr int SMEM_TOT = 174592;

__device__ __forceinline__ float tf32_rna(float x) {
    uint32_t b; asm("cvt.rna.tf32.f32 %0, %1;" : "=r"(b) : "f"(x));
    return __uint_as_float(b);
}
__device__ __forceinline__ float ex2f(float x) {
    float y; asm("ex2.approx.ftz.f32 %0, %1;" : "=f"(y) : "f"(x)); return y;
}
__device__ __forceinline__ void mma8(float* c, uint32_t a0, uint32_t a1, uint32_t a2, uint32_t a3,
                                     uint32_t b0, uint32_t b1) {
    asm volatile("mma.sync.aligned.m16n8k8.row.col.f32.tf32.tf32.f32 "
                 "{%0,%1,%2,%3},{%4,%5,%6,%7},{%8,%9},{%0,%1,%2,%3};"
                 : "+f"(c[0]), "+f"(c[1]), "+f"(c[2]), "+f"(c[3])
                 : "r"(a0), "r"(a1), "r"(a2), "r"(a3), "r"(b0), "r"(b1));
}
#define LDSM4(r, a)                                                           \
    asm volatile("ldmatrix.sync.aligned.m8n8.x4.shared.b16 {%0,%1,%2,%3},[%4];" \
                 : "=r"((r)[0]), "=r"((r)[1]), "=r"((r)[2]), "=r"((r)[3]) : "r"(a))

__device__ __forceinline__ uint32_t f2u(float x) { return __float_as_uint(x); }
__device__ __forceinline__ float4 rna4(float4 x) {
    x.x = tf32_rna(x.x); x.y = tf32_rna(x.y);
    x.z = tf32_rna(x.z); x.w = tf32_rna(x.w);
    return x;
}

// ---------------- pre-kernel: mask -> bytes (handles int32 or byte bool) ----------------
__global__ __launch_bounds__(256) void mask8k(const uint32_t* __restrict__ m) {
    __shared__ int swide;
    const int t = threadIdx.x;
    const size_t row = blockIdx.x;
    if (t == 0) {
        int wide = 1;
        for (int i = 0; i < 256; i++) {
            uint32_t x = m[i];
            if (x > 1u) { wide = (x == 0x3F800000u) ? 1 : 0; break; }
        }
        swide = wide;
    }
    __syncthreads();
    uint32_t* dst = reinterpret_cast<uint32_t*>(g_m8 + row * S);
    if (swide) {
        const uint4* src = reinterpret_cast<const uint4*>(m + row * S);
        #pragma unroll
        for (int i = 0; i < 2; i++) {
            int idx = i * 256 + t;
            uint4 x = src[idx];
            dst[idx] = (x.x ? 1u : 0u) | ((x.y ? 1u : 0u) << 8) |
                       ((x.z ? 1u : 0u) << 16) | ((x.w ? 1u : 0u) << 24);
        }
    } else {
        const uint32_t* src = reinterpret_cast<const uint32_t*>(
            reinterpret_cast<const unsigned char*>(m) + row * S);
        #pragma unroll
        for (int i = 0; i < 2; i++) {
            int idx = i * 256 + t;
            uint32_t x = src[idx];
            dst[idx] = ((x & 0xFFu) ? 1u : 0u) | (((x >> 8) & 0xFFu) ? 0x100u : 0u) |
                       (((x >> 16) & 0xFFu) ? 0x10000u : 0u) | ((x >> 24) ? 0x1000000u : 0u);
        }
    }
}

// ---------------- main kernel ----------------
__global__ __launch_bounds__(NT, 1)
void sdpa_mma(const float* __restrict__ q, const float* __restrict__ k,
              const float* __restrict__ v,
              float* __restrict__ out, float* __restrict__ wout)
{
    extern __shared__ char sm[];
    float* Qs = reinterpret_cast<float*>(sm + SM_Q);
    float* Ks = reinterpret_cast<float*>(sm + SM_K);
    float* Vs = reinterpret_cast<float*>(sm + SM_V);
    float* Ws = reinterpret_cast<float*>(sm + SM_W);
    float* Sr = reinterpret_cast<float*>(sm + SM_S);

    const uint32_t SQ = (uint32_t)__cvta_generic_to_shared(Qs);
    const uint32_t SK = (uint32_t)__cvta_generic_to_shared(Ks);
    const uint32_t SW = (uint32_t)__cvta_generic_to_shared(Ws);

    const int tid = threadIdx.x, lane = tid & 31, wid = tid >> 5;
    const int wm = wid & 3, wn = wid >> 2;             // 4(m) x 4(n)
    const int ty = lane >> 2, tx = lane & 3;

    const int bx = blockIdx.x, bh = bx >> 4, q0 = (bx & 15) * 128, b = bh >> 4;

    // ---- ldmatrix lane address components ----
    const int lr = lane & 15;            // row within 16-row fragment
    const int csel = (lane >> 4) * 4;    // word col select (tiles 2,3 -> +4 words)
    uint32_t qfb[2], wfb[2], kfb[2];
    #pragma unroll
    for (int mt = 0; mt < 2; mt++) {
        qfb[mt] = SQ + (uint32_t)(((wm * 32 + mt * 16 + lr) * PADK + csel) * 4);
        wfb[mt] = SW + (uint32_t)(((wm * 32 + mt * 16 + lr) * PADW + csel) * 4);
    }
    #pragma unroll
    for (int p = 0; p < 2; p++) {
        const int krow = wn * 32 + p * 16 + ((lane >> 4) & 1) * 8 + (lane & 7);
        kfb[p] = SK + (uint32_t)((krow * PADK + ((lane >> 3) & 1) * 4) * 4);
    }

    // ---- stage Q once (scaled, rna) ----
    {
        const float4* qg = reinterpret_cast<const float4*>(q + ((size_t)bh * S + q0) * D);
        #pragma unroll
        for (int i = 0; i < 4; i++) {
            int idx = i * NT + tid;
            int r = idx >> 4, c4 = (idx & 15) * 4;
            float4 x = qg[idx];
            x.x = tf32_rna(x.x * SCALE); x.y = tf32_rna(x.y * SCALE);
            x.z = tf32_rna(x.z * SCALE); x.w = tf32_rna(x.w * SCALE);
            *reinterpret_cast<float4*>(Qs + r * PADK + c4) = x;
        }
    }

    // ---- stage K/V tile 0 ----
    const float4* kg0 = reinterpret_cast<const float4*>(k + (size_t)bh * S * D);
    const float4* vg0 = reinterpret_cast<const float4*>(v + (size_t)bh * S * D);
    {
        #pragma unroll
        for (int i = 0; i < 4; i++) {
            int idx = i * NT + tid;
            int r = idx >> 4, c4 = (idx & 15) * 4;
            *reinterpret_cast<float4*>(Ks + r * PADK + c4) = rna4(kg0[idx]);
            *reinterpret_cast<float4*>(Vs + r * PADK + c4) = rna4(vg0[idx]);
        }
    }
    __syncthreads();

    float pacc[2][2][4];
    #pragma unroll
    for (int a = 0; a < 2; a++)
        #pragma unroll
        for (int n = 0; n < 2; n++)
            #pragma unroll
            for (int i = 0; i < 4; i++) pacc[a][n][i] = 0.f;
    float er4[4] = {0.f, 0.f, 0.f, 0.f};

    const unsigned char* mbase = g_m8 + ((size_t)b * S + q0) * S;
    float4 kpre[4], vpre[4];

    for (int jt = 0; jt < 16; jt++) {
        const int j0 = jt * 128;

        // ---- prefetch next tile into registers ----
        if (jt < 15) {
            const float4* kg = kg0 + (size_t)(j0 + 128) * (D / 4);
            const float4* vg = vg0 + (size_t)(j0 + 128) * (D / 4);
            #pragma unroll
            for (int i = 0; i < 4; i++) {
                kpre[i] = kg[i * NT + tid];
                vpre[i] = vg[i * NT + tid];
            }
        }

        // ---- QK^T: 32x32 block per warp, ldmatrix fragments ----
        float cacc[2][4][4];
        #pragma unroll
        for (int a = 0; a < 2; a++)
            #pragma unroll
            for (int n = 0; n < 4; n++)
                #pragma unroll
                for (int i = 0; i < 4; i++) cacc[a][n][i] = 0.f;

        #pragma unroll
        for (int ks = 0; ks < 8; ks++) {
            uint32_t a0[4], a1[4];
            LDSM4(a0, qfb[0] + ks * 32);
            LDSM4(a1, qfb[1] + ks * 32);
            #pragma unroll
            for (int p = 0; p < 2; p++) {
                uint32_t bb[4];
                LDSM4(bb, kfb[p] + ks * 32);
                mma8(cacc[0][2 * p],     a0[0], a0[1], a0[2], a0[3], bb[0], bb[1]);
                mma8(cacc[0][2 * p + 1], a0[0], a0[1], a0[2], a0[3], bb[2], bb[3]);
                mma8(cacc[1][2 * p],     a1[0], a1[1], a1[2], a1[3], bb[0], bb[1]);
                mma8(cacc[1][2 * p + 1], a1[0], a1[1], a1[2], a1[3], bb[2], bb[3]);
            }
        }

        // ---- mask + exp -> Ws (rna), accumulate row sums ----
        #pragma unroll
        for (int mt = 0; mt < 2; mt++) {
            const int r0 = wm * 32 + mt * 16 + ty;
            const int r1 = r0 + 8;
            const unsigned char* m0 = mbase + (size_t)r0 * S + j0 + wn * 32;
            const unsigned char* m1 = mbase + (size_t)r1 * S + j0 + wn * 32;
            #pragma unroll
            for (int nt = 0; nt < 4; nt++) {
                const int cl = wn * 32 + nt * 8 + tx * 2;
                unsigned short w0 = *reinterpret_cast<const unsigned short*>(m0 + nt * 8 + tx * 2);
                unsigned short w1 = *reinterpret_cast<const unsigned short*>(m1 + nt * 8 + tx * 2);
                float e00 = (w0 & 0xFFu) ? 1.0f : ex2f(cacc[mt][nt][0]);
                float e01 = (w0 >> 8)    ? 1.0f : ex2f(cacc[mt][nt][1]);
                float e10 = (w1 & 0xFFu) ? 1.0f : ex2f(cacc[mt][nt][2]);
                float e11 = (w1 >> 8)    ? 1.0f : ex2f(cacc[mt][nt][3]);
                e00 = tf32_rna(e00); e01 = tf32_rna(e01);
                e10 = tf32_rna(e10); e11 = tf32_rna(e11);
                er4[mt * 2 + 0] += e00 + e01;
                er4[mt * 2 + 1] += e10 + e11;
                *reinterpret_cast<float2*>(Ws + r0 * PADW + cl) = make_float2(e00, e01);
                *reinterpret_cast<float2*>(Ws + r1 * PADW + cl) = make_float2(e10, e11);
            }
        }
        __syncthreads();

        // ---- unnormalized W tile -> gmem (coalesced, streaming) ----
        {
            float* wg = wout + ((size_t)bh * S + q0) * S + j0;
            #pragma unroll
            for (int i = 0; i < 8; i++) {
                int idx = i * NT + tid;
                int r = idx >> 5, c4 = (idx & 31) * 4;
                float4 x = *reinterpret_cast<const float4*>(Ws + r * PADW + c4);
                __stcs(reinterpret_cast<float4*>(wg + (size_t)r * S + c4), x);
            }
        }

        // ---- PV: acc += W_tile @ V_tile (16 cols per warp) ----
        #pragma unroll
        for (int kk = 0; kk < 16; kk++) {
            uint32_t a0[4], a1[4];
            LDSM4(a0, wfb[0] + kk * 32);
            LDSM4(a1, wfb[1] + kk * 32);
            #pragma unroll
            for (int nt = 0; nt < 2; nt++) {
                const float* vb = Vs + (kk * 8 + tx) * PADK + wn * 16 + nt * 8 + ty;
                uint32_t b0 = f2u(vb[0]), b1 = f2u(vb[4 * PADK]);
                mma8(pacc[0][nt], a0[0], a0[1], a0[2], a0[3], b0, b1);
                mma8(pacc[1][nt], a1[0], a1[1], a1[2], a1[3], b0, b1);
            }
        }
        __syncthreads();

        // ---- store prefetched tile to smem ----
        if (jt < 15) {
            #pragma unroll
            for (int i = 0; i < 4; i++) {
                int idx = i * NT + tid;
                int r = idx >> 4, c4 = (idx & 15) * 4;
                *reinterpret_cast<float4*>(Ks + r * PADK + c4) = rna4(kpre[i]);
                *reinterpret_cast<float4*>(Vs + r * PADK + c4) = rna4(vpre[i]);
            }
            __syncthreads();
        }
    }

    // ---- row-sum reduction -> inv ----
    #pragma unroll
    for (int i = 0; i < 4; i++) {
        er4[i] += __shfl_xor_sync(0xffffffffu, er4[i], 1);
        er4[i] += __shfl_xor_sync(0xffffffffu, er4[i], 2);
    }
    if (tx == 0) {
        #pragma unroll
        for (int i = 0; i < 4; i++) {
            int r = wm * 32 + (i >> 1) * 16 + ty + (i & 1) * 8;
            Sr[wn * 128 + r] = er4[i];
        }
    }
    __syncthreads();
    if (tid < 128)
        Sr[512 + tid] = 1.0f / (Sr[tid] + Sr[128 + tid] + Sr[256 + tid] + Sr[384 + tid]);
    __syncthreads();
    const float* sinv = Sr + 512;

    // ---- write PV out (scaled) ----
    #pragma unroll
    for (int mt = 0; mt < 2; mt++) {
        const int r0 = wm * 32 + mt * 16 + ty;
        const int r1 = r0 + 8;
        const float i0 = sinv[r0], i1 = sinv[r1];
        float* o0 = out + ((size_t)bh * S + q0 + r0) * D;
        float* o1 = out + ((size_t)bh * S + q0 + r1) * D;
        #pragma unroll
        for (int nt = 0; nt < 2; nt++) {
            const int c = wn * 16 + nt * 8 + tx * 2;
            *reinterpret_cast<float2*>(o0 + c) =
                make_float2(pacc[mt][nt][0] * i0, pacc[mt][nt][1] * i0);
            *reinterpret_cast<float2*>(o1 + c) =
                make_float2(pacc[mt][nt][2] * i1, pacc[mt][nt][3] * i1);
        }
    }

    // ---- normalize this CTA's W block in place (streaming) ----
    {
        float* wg = wout + ((size_t)bh * S + q0) * S;
        #pragma unroll 4
        for (int i = 0; i < 128; i++) {
            int idx = i * NT + tid;
            int r = idx >> 9, c4 = (idx & 511) * 4;
            float4* p = reinterpret_cast<float4*>(wg + (size_t)r * S + c4);
            float4 x = __ldcs(p);
            const float iv = sinv[r];
            x.x *= iv; x.y *= iv; x.z *= iv; x.w *= iv;
            __stcs(p, x);
        }
    }
}

extern "C" void kernel_launch(void* const* d_in, const int* in_sizes, int n_in,
                              void* d_out, int out_size)
{
    const float* q = (const float*)d_in[0];
    const float* k = (const float*)d_in[1];
    const float* v = (const float*)d_in[2];
    const uint32_t* mask = (const uint32_t*)d_in[3];

    float* out  = (float*)d_out;
    float* wout = out + (size_t)B * H * S * D;

    static bool configured = false;
    if (!configured) {
        cudaFuncSetAttribute(sdpa_mma, cudaFuncAttributeMaxDynamicSharedMemorySize, SMEM_TOT);
        configured = true;
    }
    mask8k<<<B * S, 256>>>(mask);
    sdpa_mma<<<B * H * 16, NT, SMEM_TOT>>>(q, k, v, out, wout);
}